// round 16
// baseline (speedup 1.0000x reference)
#include <cuda_runtime.h>
#include <cuda_bf16.h>
#include <math.h>
#include <stdint.h>

// ---------------- problem constants ----------------
#define BATCH 64
#define CCH   256
#define NTOK  400
#define TOKS  (BATCH*NTOK) // 25600

// ---------------- scratch layout (float units) ----------------
constexpr size_t O_XT    = 0;                          // fp32 TOKS*256
constexpr size_t O_XTH   = O_XT    + (size_t)TOKS*256; // bf16 TOKS*256
constexpr size_t O_G     = O_XTH   + (size_t)TOKS*128; // bf16 token-major
constexpr size_t O_QP    = O_G     + (size_t)TOKS*128; // bf16 token-major
constexpr size_t O_QN    = O_QP    + (size_t)TOKS*128;
constexpr size_t O_KP    = O_QN    + (size_t)TOKS*128;
constexpr size_t O_KN    = O_KP    + (size_t)TOKS*128;
constexpr size_t O_VF    = O_KN    + (size_t)TOKS*128; // bf16 flat
constexpr size_t O_VD    = O_VF    + (size_t)TOKS*128; // bf16 flat
constexpr size_t O_KM    = O_VD    + (size_t)TOKS*128;
constexpr size_t O_KVS   = O_KM    + (size_t)512*64;
constexpr size_t O_KVO   = O_KVS   + (size_t)512*1024;
constexpr size_t O_OUT2H = O_KVO   + (size_t)512*1024; // bf16 token-major
constexpr size_t O_S     = O_OUT2H + (size_t)TOKS*128; // fp32
constexpr size_t O_SH    = O_S     + (size_t)TOKS*256; // bf16
constexpr size_t O_YH    = O_SH    + (size_t)TOKS*128; // bf16 TOKS*1024
constexpr size_t O_Y2H   = O_YH    + (size_t)TOKS*512; // bf16 TOKS*512
constexpr size_t O_TMP   = O_Y2H   + (size_t)TOKS*256; // fp32
constexpr size_t O_SE    = O_TMP   + (size_t)TOKS*256;
constexpr size_t O_INV   = O_SE    + (size_t)BATCH*512;
constexpr size_t O_PW    = O_INV   + 256;
constexpr size_t O_WPJH  = O_PW    + 256;               // bf16 256*256
constexpr size_t O_WPIH  = O_WPJH  + 32768;             // bf16 1024*256
constexpr size_t O_WPOH  = O_WPIH  + 131072;            // bf16 256*512
constexpr size_t O_WQH   = O_WPOH  + 65536;             // bf16 512*256
constexpr size_t O_WKH   = O_WQH   + 65536;             // bf16 512*256
constexpr size_t SCR_TOTAL = O_WKH + 65536;

__device__ __align__(256) float d_scratch[SCR_TOTAL];

// =======================================================================
// helpers
// =======================================================================
__device__ __forceinline__ uint32_t smem_u32(const void* p) {
    uint32_t a;
    asm("{ .reg .u64 t; cvta.to.shared.u64 t, %1; cvt.u32.u64 %0, t; }" : "=r"(a) : "l"(p));
    return a;
}
__device__ __forceinline__ void cp16(uint32_t s, const void* g) {
    asm volatile("cp.async.ca.shared.global [%0], [%1], 16;" :: "r"(s), "l"(g));
}
#define CP_COMMIT() asm volatile("cp.async.commit_group;" ::: "memory")
#define CP_WAIT(n)  asm volatile("cp.async.wait_group %0;" :: "n"(n) : "memory")

__device__ __forceinline__ void mma_bf16(float* d, const uint32_t* a, const uint32_t* b) {
    asm volatile(
        "mma.sync.aligned.m16n8k16.row.col.f32.bf16.bf16.f32 "
        "{%0,%1,%2,%3}, {%4,%5,%6,%7}, {%8,%9}, {%0,%1,%2,%3};"
        : "+f"(d[0]), "+f"(d[1]), "+f"(d[2]), "+f"(d[3])
        : "r"(a[0]), "r"(a[1]), "r"(a[2]), "r"(a[3]), "r"(b[0]), "r"(b[1]));
}
__device__ __forceinline__ void ldm_x4(uint32_t* r, uint32_t addr) {
    asm volatile("ldmatrix.sync.aligned.m8n8.x4.shared.b16 {%0,%1,%2,%3}, [%4];"
        : "=r"(r[0]), "=r"(r[1]), "=r"(r[2]), "=r"(r[3]) : "r"(addr));
}
__device__ __forceinline__ void ldm_x2(uint32_t* r, uint32_t addr) {
    asm volatile("ldmatrix.sync.aligned.m8n8.x2.shared.b16 {%0,%1}, [%2];"
        : "=r"(r[0]), "=r"(r[1]) : "r"(addr));
}

constexpr int HROWB = 144;                 // bytes per smem row (64 bf16 + pad)
constexpr int HB_TILE_B = 128 * HROWB;     // 18432
constexpr int HB_STAGE  = 2 * HB_TILE_B;   // 36864
constexpr int SMEM_GBF  = 3 * HB_STAGE;    // 110592 (3-stage)

// =======================================================================
// gemm_qgkv_bf: merged qg + kv GEMMs. grid (4, 200, 2). 3-stage, ldmatrix.
// =======================================================================
__global__ __launch_bounds__(256, 2)
void gemm_qgkv_bf(const __nv_bfloat16* __restrict__ A,
                  const __nv_bfloat16* __restrict__ wq, const float* __restrict__ bq,
                  const __nv_bfloat16* __restrict__ wk, const float* __restrict__ bk,
                  const float* __restrict__ pos,
                  const float* __restrict__ invsc, const float* __restrict__ pw,
                  __nv_bfloat16* __restrict__ QP, __nv_bfloat16* __restrict__ QN,
                  __nv_bfloat16* __restrict__ G,
                  __nv_bfloat16* __restrict__ KP, __nv_bfloat16* __restrict__ KN,
                  __nv_bfloat16* __restrict__ VF) {
    const int K = 256;
    extern __shared__ float sm[];
    const uint32_t sbase = smem_u32(sm);
    const int t = threadIdx.x, lane = t & 31, wid = t >> 5;
    const int wm = (wid >> 2) * 64;
    const int wn = (wid & 3) * 32;
    const int bm = blockIdx.y * 128, bn = blockIdx.x * 128;
    const int g4 = lane >> 2, l4 = lane & 3;
    const bool isKV = (blockIdx.z != 0);
    const __nv_bfloat16* Bw = isKV ? wk : wq;
    const float* bias = isKV ? bk : bq;

    const uint32_t a_lo = (uint32_t)((wm + (lane & 7) + ((lane >> 3) & 1) * 8) * HROWB
                                     + ((lane >> 4) & 1) * 16);
    const int lbi = lane & 15;
    const uint32_t b_lo = (uint32_t)((wn + (lbi & 7)) * HROWB + ((lbi >> 3) & 1) * 16);

    auto load_chunk = [&](int ch, int buf) {
        int k0 = ch << 6;
        uint32_t sb = sbase + (uint32_t)buf * HB_STAGE;
#pragma unroll
        for (int i = 0; i < 8; i++) {
            int o = t + i * 256;
            int isB = o >> 10;
            int row = (o & 1023) >> 3;
            int seg = o & 7;
            const __nv_bfloat16* g = (isB ? Bw + (size_t)(bn + row) * K
                                          : A  + (size_t)(bm + row) * K) + k0 + seg * 8;
            uint32_t s = sb + (uint32_t)(isB * HB_TILE_B + row * HROWB + seg * 16);
            cp16(s, g);
        }
        CP_COMMIT();
    };

    float acc[4][4][4];
#pragma unroll
    for (int mi = 0; mi < 4; mi++)
#pragma unroll
        for (int ni = 0; ni < 4; ni++)
#pragma unroll
            for (int k = 0; k < 4; k++) acc[mi][ni][k] = 0.0f;

    const int NC = 4;
    load_chunk(0, 0);
    load_chunk(1, 1);
    for (int ch = 0; ch < NC; ch++) {
        if (ch == NC - 1) { CP_WAIT(0); } else { CP_WAIT(1); }
        __syncthreads();
        if (ch + 2 < NC) load_chunk(ch + 2, (ch + 2) % 3);
        uint32_t Ab = sbase + (uint32_t)((ch % 3) * HB_STAGE);
        uint32_t Bb = Ab + HB_TILE_B;
#pragma unroll
        for (int s = 0; s < 4; s++) {
            uint32_t ah[4][4], bh[4][2];
#pragma unroll
            for (int mi = 0; mi < 4; mi++)
                ldm_x4(ah[mi], Ab + a_lo + (uint32_t)(mi * 16 * HROWB + s * 32));
#pragma unroll
            for (int ni = 0; ni < 4; ni++)
                ldm_x2(bh[ni], Bb + b_lo + (uint32_t)(ni * 8 * HROWB + s * 32));
#pragma unroll
            for (int mi = 0; mi < 4; mi++)
#pragma unroll
                for (int ni = 0; ni < 4; ni++)
                    mma_bf16(acc[mi][ni], ah[mi], bh[ni]);
        }
    }

    bool first_half = (bn < 256);
#pragma unroll
    for (int mi = 0; mi < 4; mi++) {
#pragma unroll
        for (int half = 0; half < 2; half++) {
            int r = bm + wm + mi * 16 + g4 + half * 8;
            int tok = r % NTOK;
#pragma unroll
            for (int ni = 0; ni < 4; ni++) {
                int cb = bn + wn + ni * 8 + 2 * l4;
                float v0 = acc[mi][ni][half * 2 + 0] + bias[cb];
                float v1 = acc[mi][ni][half * 2 + 1] + bias[cb + 1];
                if (first_half) {
                    float xp0 = 0.f, xn0 = 0.f, xp1 = 0.f, xn1 = 0.f;
#pragma unroll
                    for (int j = 0; j < 2; j++) {
                        int ccol = cb + j;
                        float v = j ? v1 : v0;
                        float x = isKV ? (v + pos[(size_t)tok * 256 + ccol]) * invsc[ccol]
                                       : v * invsc[ccol];
                        float p = pw[ccol];
                        float xp = 0.f, xn = 0.f;
                        if (x > 0.f)      xp = __powf(fmaxf(x, 1e-30f), p);
                        else if (x < 0.f) xn = __powf(fmaxf(-x, 1e-30f), p);
                        if (j) { xp1 = xp; xn1 = xn; } else { xp0 = xp; xn0 = xn; }
                    }
                    __nv_bfloat16* P1 = isKV ? KP : QP;
                    __nv_bfloat16* P2 = isKV ? KN : QN;
                    *(__nv_bfloat162*)&P1[(size_t)r * 256 + cb] =
                        __floats2bfloat162_rn(xp0, xp1);
                    *(__nv_bfloat162*)&P2[(size_t)r * 256 + cb] =
                        __floats2bfloat162_rn(xn0, xn1);
                } else {
                    int cc = cb - 256;
                    __nv_bfloat16* P3 = isKV ? VF : G;
                    *(__nv_bfloat162*)&P3[(size_t)r * 256 + cc] =
                        __floats2bfloat162_rn(v0, v1);
                }
            }
        }
    }
}

// =======================================================================
// gemm_bf: bf16 GEMM, 3-stage, ldmatrix. OB: bf16 output.
// =======================================================================
template<bool OB>
__global__ __launch_bounds__(256, 2)
void gemm_bf(const __nv_bfloat16* __restrict__ A, const __nv_bfloat16* __restrict__ Bw,
             void* __restrict__ Cv, int M, int N, int K) {
    extern __shared__ float sm[];
    const uint32_t sbase = smem_u32(sm);
    const int t = threadIdx.x, lane = t & 31, wid = t >> 5;
    const int wm = (wid >> 2) * 64;
    const int wn = (wid & 3) * 32;
    const int bm = blockIdx.y * 128, bn = blockIdx.x * 128;
    const int g4 = lane >> 2, l4 = lane & 3;
    const int NC = K >> 6;

    const uint32_t a_lo = (uint32_t)((wm + (lane & 7) + ((lane >> 3) & 1) * 8) * HROWB
                                     + ((lane >> 4) & 1) * 16);
    const int lbi = lane & 15;
    const uint32_t b_lo = (uint32_t)((wn + (lbi & 7)) * HROWB + ((lbi >> 3) & 1) * 16);

    auto load_chunk = [&](int ch, int buf) {
        int k0 = ch << 6;
        uint32_t sb = sbase + (uint32_t)buf * HB_STAGE;
#pragma unroll
        for (int i = 0; i < 8; i++) {
            int o = t + i * 256;
            int isB = o >> 10;
            int row = (o & 1023) >> 3;
            int seg = o & 7;
            const __nv_bfloat16* g = (isB ? Bw + (size_t)(bn + row) * K
                                          : A  + (size_t)(bm + row) * K) + k0 + seg * 8;
            uint32_t s = sb + (uint32_t)(isB * HB_TILE_B + row * HROWB + seg * 16);
            cp16(s, g);
        }
        CP_COMMIT();
    };

    float acc[4][4][4];
#pragma unroll
    for (int mi = 0; mi < 4; mi++)
#pragma unroll
        for (int ni = 0; ni < 4; ni++)
#pragma unroll
            for (int k = 0; k < 4; k++) acc[mi][ni][k] = 0.0f;

    load_chunk(0, 0);
    if (NC > 1) load_chunk(1, 1);

    for (int ch = 0; ch < NC; ch++) {
        if (ch == NC - 1) { CP_WAIT(0); } else { CP_WAIT(1); }
        __syncthreads();
        if (ch + 2 < NC) load_chunk(ch + 2, (ch + 2) % 3);
        uint32_t Ab = sbase + (uint32_t)((ch % 3) * HB_STAGE);
        uint32_t Bb = Ab + HB_TILE_B;
#pragma unroll
        for (int s = 0; s < 4; s++) {
            uint32_t ah[4][4], bh[4][2];
#pragma unroll
            for (int mi = 0; mi < 4; mi++)
                ldm_x4(ah[mi], Ab + a_lo + (uint32_t)(mi * 16 * HROWB + s * 32));
#pragma unroll
            for (int ni = 0; ni < 4; ni++)
                ldm_x2(bh[ni], Bb + b_lo + (uint32_t)(ni * 8 * HROWB + s * 32));
#pragma unroll
            for (int mi = 0; mi < 4; mi++)
#pragma unroll
                for (int ni = 0; ni < 4; ni++)
                    mma_bf16(acc[mi][ni], ah[mi], bh[ni]);
        }
    }

#pragma unroll
    for (int mi = 0; mi < 4; mi++) {
        int r0 = bm + wm + mi * 16 + g4;
#pragma unroll
        for (int ni = 0; ni < 4; ni++) {
            int cb = bn + wn + ni * 8 + 2 * l4;
            if (OB) {
                __nv_bfloat16* C = (__nv_bfloat16*)Cv;
                *(__nv_bfloat162*)&C[(size_t)r0 * N + cb] =
                    __floats2bfloat162_rn(acc[mi][ni][0], acc[mi][ni][1]);
                *(__nv_bfloat162*)&C[(size_t)(r0 + 8) * N + cb] =
                    __floats2bfloat162_rn(acc[mi][ni][2], acc[mi][ni][3]);
            } else {
                float* C = (float*)Cv;
                *(float2*)&C[(size_t)r0 * N + cb]       = make_float2(acc[mi][ni][0], acc[mi][ni][1]);
                *(float2*)&C[(size_t)(r0 + 8) * N + cb] = make_float2(acc[mi][ni][2], acc[mi][ni][3]);
            }
        }
    }
}

// =======================================================================
// gemm_bf_ln: OUT = LN( RES + A@Bw^T (+bias) ), N=256, 512 thr, 2-stage, ldmatrix.
// =======================================================================
constexpr int HL_TA_B  = 128 * HROWB;
constexpr int HL_STAGE = (128 + 256) * HROWB;   // 55296
constexpr int SMEM_GBLN = 2 * HL_STAGE;         // 110592

template<int KD, bool WH>
__global__ __launch_bounds__(512)
void gemm_bf_ln(const __nv_bfloat16* __restrict__ A, const __nv_bfloat16* __restrict__ Bw,
                const float* __restrict__ bias, const float* __restrict__ RES,
                const float* __restrict__ lw, const float* __restrict__ lb,
                float* __restrict__ OUT, __nv_bfloat16* __restrict__ OUTH) {
    const int N = 256;
    extern __shared__ float sm[];
    const uint32_t sbase = smem_u32(sm);
    const int t = threadIdx.x, lane = t & 31, wid = t >> 5;
    const int wm = (wid >> 2) * 32;
    const int wn = (wid & 3) * 64;
    const int bm = blockIdx.x * 128;
    const int g4 = lane >> 2, l4 = lane & 3;
    const int NC = KD >> 6;

    const uint32_t a_lo = (uint32_t)((wm + (lane & 7) + ((lane >> 3) & 1) * 8) * HROWB
                                     + ((lane >> 4) & 1) * 16);
    const int lbi = lane & 15;
    const uint32_t b_lo = (uint32_t)((wn + (lbi & 7)) * HROWB + ((lbi >> 3) & 1) * 16);

    auto load_chunk = [&](int ch, int buf) {
        int k0 = ch << 6;
        uint32_t sb = sbase + (uint32_t)buf * HL_STAGE;
#pragma unroll
        for (int i = 0; i < 6; i++) {
            int o = t + i * 512;
            bool isB = o >= 1024;
            int row = isB ? ((o - 1024) >> 3) : (o >> 3);
            int seg = o & 7;
            const __nv_bfloat16* g = (isB ? Bw + (size_t)row * KD
                                          : A  + (size_t)(bm + row) * KD) + k0 + seg * 8;
            uint32_t s = sb + (uint32_t)((isB ? HL_TA_B : 0) + row * HROWB + seg * 16);
            cp16(s, g);
        }
        CP_COMMIT();
    };

    float acc[2][8][4];
#pragma unroll
    for (int mi = 0; mi < 2; mi++)
#pragma unroll
        for (int ni = 0; ni < 8; ni++)
#pragma unroll
            for (int k = 0; k < 4; k++) acc[mi][ni][k] = 0.0f;

    load_chunk(0, 0);
    if (NC > 1) load_chunk(1, 1);

    for (int ch = 0; ch < NC; ch++) {
        if (ch + 1 < NC) { CP_WAIT(1); } else { CP_WAIT(0); }
        __syncthreads();
        uint32_t Ab = sbase + (uint32_t)((ch & 1) * HL_STAGE);
        uint32_t Bb = Ab + HL_TA_B;
#pragma unroll
        for (int s = 0; s < 4; s++) {
            uint32_t af[2][4], bf[8][2];
#pragma unroll
            for (int mi = 0; mi < 2; mi++)
                ldm_x4(af[mi], Ab + a_lo + (uint32_t)(mi * 16 * HROWB + s * 32));
#pragma unroll
            for (int ni = 0; ni < 8; ni++)
                ldm_x2(bf[ni], Bb + b_lo + (uint32_t)(ni * 8 * HROWB + s * 32));
#pragma unroll
            for (int mi = 0; mi < 2; mi++)
#pragma unroll
                for (int ni = 0; ni < 8; ni++)
                    mma_bf16(acc[mi][ni], af[mi], bf[ni]);
        }
        __syncthreads();
        if (ch + 2 < NC) load_chunk(ch + 2, ch & 1);
    }

    __syncthreads();
    float* ssum = sm;
    float* ssq  = sm + 512;

#pragma unroll
    for (int mi = 0; mi < 2; mi++)
#pragma unroll
        for (int half = 0; half < 2; half++) {
            int r = bm + wm + mi * 16 + g4 + half * 8;
#pragma unroll
            for (int ni = 0; ni < 8; ni++)
#pragma unroll
                for (int j = 0; j < 2; j++) {
                    int c = wn + ni * 8 + 2 * l4 + j;
                    float b = bias ? bias[c] : 0.f;
                    acc[mi][ni][half * 2 + j] += b + RES[(size_t)r * N + c];
                }
        }
#pragma unroll
    for (int mi = 0; mi < 2; mi++)
#pragma unroll
        for (int half = 0; half < 2; half++) {
            float s = 0.f, q = 0.f;
#pragma unroll
            for (int ni = 0; ni < 8; ni++)
#pragma unroll
                for (int j = 0; j < 2; j++) {
                    float v = acc[mi][ni][half * 2 + j];
                    s += v; q += v * v;
                }
            s += __shfl_xor_sync(0xffffffffu, s, 1);
            s += __shfl_xor_sync(0xffffffffu, s, 2);
            q += __shfl_xor_sync(0xffffffffu, q, 1);
            q += __shfl_xor_sync(0xffffffffu, q, 2);
            if (l4 == 0) {
                int lr = wm + mi * 16 + g4 + half * 8;
                ssum[(wid & 3) * 128 + lr] = s;
                ssq[(wid & 3) * 128 + lr]  = q;
            }
        }
    __syncthreads();
#pragma unroll
    for (int mi = 0; mi < 2; mi++)
#pragma unroll
        for (int half = 0; half < 2; half++) {
            int lr = wm + mi * 16 + g4 + half * 8;
            float s = ssum[lr] + ssum[128 + lr] + ssum[256 + lr] + ssum[384 + lr];
            float q = ssq[lr]  + ssq[128 + lr]  + ssq[256 + lr]  + ssq[384 + lr];
            float mean = s * (1.0f / 256.0f);
            float var  = q * (1.0f / 256.0f) - mean * mean;
            float inv  = rsqrtf(var + 1e-6f);
            int r = bm + lr;
#pragma unroll
            for (int ni = 0; ni < 8; ni++)
#pragma unroll
                for (int j = 0; j < 2; j++) {
                    int c = wn + ni * 8 + 2 * l4 + j;
                    float v = acc[mi][ni][half * 2 + j];
                    float o = lw[c] * (v - mean) * inv + lb[c];
                    OUT[(size_t)r * N + c] = o;
                    if (WH) OUTH[(size_t)r * N + c] = __float2bfloat16(o);
                }
        }
}

// ---------------- weight -> bf16 convert + param prep ----------------
__global__ void k_cvtw(const float* __restrict__ p1, __nv_bfloat16* __restrict__ o1, int n1,
                       const float* __restrict__ p2, __nv_bfloat16* __restrict__ o2, int n2,
                       const float* __restrict__ p3, __nv_bfloat16* __restrict__ o3, int n3,
                       const float* __restrict__ p4, __nv_bfloat16* __restrict__ o4, int n4,
                       const float* __restrict__ p5, __nv_bfloat16* __restrict__ o5, int n5,
                       const float* __restrict__ scale, const float* __restrict__ power,
                       float* __restrict__ invsc, float* __restrict__ pw) {
    if (blockIdx.x == 0 && threadIdx.x < 256) {
        int c = threadIdx.x;
        float sp = log1pf(expf(scale[c]));
        invsc[c] = 1.0f / sp;
        pw[c] = 1.0f + 4.0f / (1.0f + expf(-power[c]));
    }
    int total = n1 + n2 + n3 + n4 + n5;
    for (int i = blockIdx.x * blockDim.x + threadIdx.x; i < total; i += gridDim.x * blockDim.x) {
        int r = i;
        if (r < n1) { o1[r] = __float2bfloat16(p1[r]); continue; } r -= n1;
        if (r < n2) { o2[r] = __float2bfloat16(p2[r]); continue; } r -= n2;
        if (r < n3) { o3[r] = __float2bfloat16(p3[r]); continue; } r -= n3;
        if (r < n4) { o4[r] = __float2bfloat16(p4[r]); continue; } r -= n4;
        o5[r] = __float2bfloat16(p5[r]);
    }
}

// ---------------- transpose (B,C,400) -> (B,400,C) fp32 + bf16 ----------------
__global__ void k_tr_src(const float* __restrict__ src, float* __restrict__ XT,
                         __nv_bfloat16* __restrict__ XTH) {
    __shared__ float tile[32][33];
    int b = blockIdx.z, cb = blockIdx.y * 32, nb = blockIdx.x * 32;
    int tx = threadIdx.x, ty = threadIdx.y;
    int n = nb + tx, c = cb + ty;
    if (n < NTOK) tile[ty][tx] = src[(size_t)b*CCH*NTOK + (size_t)c*NTOK + n];
    __syncthreads();
    n = nb + ty; c = cb + tx;
    if (n < NTOK) {
        float v = tile[tx][ty];
        size_t o = ((size_t)b*NTOK + n)*CCH + c;
        XT[o] = v;
        XTH[o] = __float2bfloat16(v);
    }
}

// ---------------- transpose (B,400,C) -> (B,C,400) ----------------
__global__ void k_tr_out(const float* __restrict__ TMP, float* __restrict__ OUT) {
    __shared__ float tile[32][33];
    int b = blockIdx.z, cb = blockIdx.y * 32, nb = blockIdx.x * 32;
    int tx = threadIdx.x, ty = threadIdx.y;
    int n = nb + ty, c = cb + tx;
    if (n < NTOK) tile[ty][tx] = TMP[((size_t)b*NTOK + n)*CCH + c];
    __syncthreads();
    c = cb + ty; n = nb + tx;
    if (n < NTOK) OUT[(size_t)b*CCH*NTOK + (size_t)c*NTOK + n] = tile[tx][ty];
}

// =======================================================================
// k_fused: [0,512) reductions (80-token chunks);
//          [512,1536) dwc5x5 (row-streaming, 5 LDS/row, weights in regs);
//          [1536,1600) SE
// =======================================================================
__global__ __launch_bounds__(256)
void k_fused(const __nv_bfloat16* __restrict__ KP, const __nv_bfloat16* __restrict__ KN,
             const __nv_bfloat16* __restrict__ VF,
             float* __restrict__ KM, float* __restrict__ KVS, float* __restrict__ KVO,
             const float* __restrict__ dwcw, const float* __restrict__ dwcb,
             __nv_bfloat16* __restrict__ VD,
             const float* __restrict__ src, const float* __restrict__ sew,
             float* __restrict__ SE) {
    __shared__ float fsm[14*640];
    int bid = blockIdx.x;
    int t = threadIdx.x;

    if (bid < 512) {
        float* kc_s = fsm;            // [80][64]
        float* v_s  = fsm + 5120;     // [80][32]
        int bh = bid, b = bh >> 3, h = bh & 7;
        int j = t >> 2, e0 = (t & 3) << 2;
        float accs[4] = {0,0,0,0}, acco[4] = {0,0,0,0}, accm = 0.f;
        for (int n0 = 0; n0 < NTOK; n0 += 80) {
#pragma unroll
            for (int rr = 0; rr < 10; rr++) {
                int idx = t + rr * 256;
                int nl = idx >> 5, j2 = idx & 31;
                size_t row = ((size_t)(b*NTOK + n0 + nl))*256 + h*32;
                __nv_bfloat162 pr = (j2 < 16)
                    ? *(const __nv_bfloat162*)&KP[row + 2*j2]
                    : *(const __nv_bfloat162*)&KN[row + 2*(j2-16)];
                float2 f = __bfloat1622float2(pr);
                *(float2*)&kc_s[nl*64 + 2*j2] = f;
            }
#pragma unroll
            for (int rr = 0; rr < 5; rr++) {
                int idx = t + rr * 256;
                int nl = idx >> 4, e2 = idx & 15;
                int ee = 2*e2;
                size_t row = ((size_t)(b*NTOK + n0 + nl))*256;
                size_t base = (ee < 16) ? row + h*16 + ee : row + 128 + h*16 + (ee-16);
                float2 f = __bfloat1622float2(*(const __nv_bfloat162*)&VF[base]);
                *(float2*)&v_s[nl*32 + ee] = f;
            }
            __syncthreads();
#pragma unroll 4
            for (int nl = 0; nl < 80; nl++) {
                float kcv = kc_s[nl*64 + j];
                accm += kcv;
                float4 vs = *(const float4*)&v_s[nl*32 + e0];
                float4 vo = *(const float4*)&v_s[nl*32 + 16 + e0];
                accs[0] += kcv*vs.x; accs[1] += kcv*vs.y;
                accs[2] += kcv*vs.z; accs[3] += kcv*vs.w;
                acco[0] += kcv*vo.x; acco[1] += kcv*vo.y;
                acco[2] += kcv*vo.z; acco[3] += kcv*vo.w;
            }
            __syncthreads();
        }
        const float invN = 1.0f / (float)NTOK;
        size_t ob = (size_t)bh*1024 + (size_t)j*16 + e0;
#pragma unroll
        for (int q = 0; q < 4; q++) { KVS[ob+q] = accs[q]*invN; KVO[ob+q] = acco[q]*invN; }
        if ((t & 3) == 0) KM[(size_t)bh*64 + j] = accm * invN;
    } else if (bid < 1536) {
        float* tile = fsm;
        int blk = bid - 512;
        int half = blk & 1, g = (blk >> 1) & 7, b = blk >> 4;
        int dd = t & 31;
        float wreg[25];
#pragma unroll
        for (int k = 0; k < 25; k++) wreg[k] = dwcw[dd*25 + k];
        float bsv = dwcb[dd];
        const __nv_bfloat16* Vb = VF + (size_t)b*102400 + (size_t)g*12800;
        int r0 = half*10 - 2;
        for (int i = t; i < 14*80; i += 256) {
            int rr = i / 80, seg = i - rr*80;
            int r = r0 + rr;
            float4 f0 = make_float4(0,0,0,0), f1 = make_float4(0,0,0,0);
            if (r >= 0 && r < 20) {
                uint4 u = *(const uint4*)(Vb + r*640 + seg*8);
                float2 q0 = __bfloat1622float2(*(__nv_bfloat162*)&u.x);
                float2 q1 = __bfloat1622float2(*(__nv_bfloat162*)&u.y);
                float2 q2 = __bfloat1622float2(*(__nv_bfloat162*)&u.z);
                float2 q3 = __bfloat1622float2(*(__nv_bfloat162*)&u.w);
                f0 = make_float4(q0.x, q0.y, q1.x, q1.y);
                f1 = make_float4(q2.x, q2.y, q3.x, q3.y);
            }
            *(float4*)&tile[rr*640 + seg*8]     = f0;
            *(float4*)&tile[rr*640 + seg*8 + 4] = f1;
        }
        __syncthreads();
        // row-streaming compute: thread owns columns col = t, t+256, t+512
        // (dd = col & 31 is constant since 256 % 32 == 0)
        size_t outbase = (size_t)b*102400 + (size_t)g*12800;
        for (int col = t; col < 640; col += 256) {
            int x = col >> 5;
            bool vld[5];
            int xo[5];
#pragma unroll
            for (int kx = 0; kx < 5; kx++) {
                int xx = x + kx - 2;
                vld[kx] = (xx >= 0 && xx < 20);
                xo[kx] = xx * 32 + dd;
            }
            float acc[5];
#pragma unroll
            for (int i = 0; i < 5; i++) acc[i] = bsv;
#pragma unroll
            for (int r = 0; r < 14; r++) {
                float vals[5];
#pragma unroll
                for (int kx = 0; kx < 5; kx++)
                    vals[kx] = vld[kx] ? tile[r*640 + xo[kx]] : 0.f;
#pragma unroll
                for (int yl = 0; yl < 10; yl++) {
                    if (yl > r || yl < r - 4) continue;   // compile-time pruned
                    int ky = r - yl;
                    float s = vals[0] * wreg[ky*5 + 0];
                    s += vals[1] * wreg[ky*5 + 1];
                    s += vals[2] * wreg[ky*5 + 2];
                    s += vals[3] * wreg[ky*5 + 3];
                    s += vals[4] * wreg[ky*5 + 4];
                    acc[yl % 5] += s;
                }
                if (r >= 4) {
                    int yl = r - 4;
                    int y = half*10 + yl;
                    VD[outbase + (size_t)y*640 + col] = __float2bfloat16(acc[yl % 5]);
                    acc[yl % 5] = bsv;
                }
            }
        }
    } else {
        float* smv = fsm;
        int b = bid - 1536;
        int w = t >> 5, lane = t & 31;
        for (int ci = 0; ci < 32; ci++) {
            int c = w*32 + ci;
            const float* p = src + (size_t)b*102400 + (size_t)c*400;
            float s = 0.f;
            for (int n = lane; n < 400; n += 32) s += p[n];
#pragma unroll
            for (int off = 16; off; off >>= 1) s += __shfl_xor_sync(0xffffffffu, s, off);
            if (lane == 0) smv[c] = s * (1.0f/400.0f);
        }
        __syncthreads();
        for (int o = t; o < 512; o += 256) {
            const float4* wr = (const float4*)(sew + (size_t)o*256);
            float acc = 0.f;
#pragma unroll 8
            for (int c4 = 0; c4 < 64; c4++) {
                float4 w4 = wr[c4];
                float4 s4 = *(const float4*)&smv[c4*4];
                acc += w4.x*s4.x + w4.y*s4.y + w4.z*s4.z + w4.w*s4.w;
            }
            SE[(size_t)b*512 + o] = 1.0f / (1.0f + expf(-acc));
        }
    }
}

// ---------------- attention output + vd + gate ----------------
__global__ __launch_bounds__(256)
void k_attn_out(const __nv_bfloat16* __restrict__ QP, const __nv_bfloat16* __restrict__ QN,
                const float* __restrict__ KM, const float* __restrict__ KVS,
                const float* __restrict__ KVO, const __nv_bfloat16* __restrict__ VD,
                const __nv_bfloat16* __restrict__ G, __nv_bfloat16* __restrict__ OUT2H) {
    int bh = blockIdx.x, b = bh >> 3, h = bh & 7;
    __shared__ float km_s[64];
    __shared__ float kvb[64][32];
    __shared__ float qps[8][32], qns[8][32];
    int t = threadIdx.x, w = t >> 5, d = t & 31;
    for (int idx = t; idx < 64; idx += 256) km_s[idx] = KM[(size_t)bh*64 + idx];
    for (int idx = t; idx < 2048; idx += 256) {
        int j = idx >> 5, col = idx & 31;
        kvb[j][col] = (col < 16) ? KVS[(size_t)bh*1024 + j*16 + col]
                                 : KVO[(size_t)bh*1024 + j*16 + (col - 16)];
    }
    __syncthreads();
    bool sim = (d < 16);
    for (int n0 = 0; n0 < NTOK; n0 += 8) {
        int n = n0 + w;
        size_t tokbase = ((size_t)(b*NTOK + n)) * 256;
        float qp = __bfloat162float(QP[tokbase + h*32 + d]);
        float qn = __bfloat162float(QN[tokbase + h*32 + d]);
        qps[w][d] = qp; qns[w][d] = qn;
        __syncwarp();
        float d1 = qp*km_s[d] + qn*km_s[32 + d];
        float d2 = qn*km_s[d] + qp*km_s[32 + d];
#pragma unroll
        for (int off = 16; off; off >>= 1) {
            d1 += __shfl_xor_sync(0xffffffffu, d1, off);
            d2 += __shfl_xor_sync(0xffffffffu, d2, off);
        }
        float acc = 0.f;
#pragma unroll
        for (int j = 0; j < 32; j++) {
            float a = qps[w][j], bb = qns[w][j];
            float m1 = sim ? a : bb;
            float m2 = sim ? bb : a;
            acc += m1*kvb[j][d] + m2*kvb[32 + j][d];
        }
        float den = (sim ? d1 : d2) + 1e-6f;
        float val = acc / den;
        int c = h*32 + d;
        float vdv = __bfloat162float(VD[tokbase + c]);
        float gg  = __bfloat162float(G[tokbase + c]);
        OUT2H[tokbase + c] = __float2bfloat16((val + vdv) * gg);
        __syncwarp();
    }
}

// ---------------- dw3x3 + GLU(gelu) + SE scale — SMEM tiled ----------------
constexpr int DG_CH  = 128;
constexpr int DG_TROW = 20 * DG_CH;
constexpr int DG_TILE = 7 * DG_TROW;
constexpr int SMEM_DG = (2 * DG_TILE + 2 * DG_CH * 9 + DG_CH) * 4;

__global__ __launch_bounds__(256)
void k_dw_glu(const __nv_bfloat16* __restrict__ Y, const float* __restrict__ dww,
              const float* __restrict__ SE, __nv_bfloat16* __restrict__ Y2H) {
    extern __shared__ float dsm[];
    float* s1t = dsm;
    float* s2t = dsm + DG_TILE;
    float* w1  = dsm + 2 * DG_TILE;
    float* w2  = w1 + DG_CH * 9;
    float* ses = w2 + DG_CH * 9;

    int cq = blockIdx.x, ys = blockIdx.y, b = blockIdx.z;
    int t = threadIdx.x;
    int ch0 = cq * DG_CH;
    int y0 = ys * 5;

    for (int i = t; i < DG_CH * 9; i += 256) {
        int ch = i / 9, k = i % 9;
        w1[i] = dww[(ch0 + ch) * 9 + k];
        w2[i] = dww[(512 + ch0 + ch) * 9 + k];
    }
    if (t < DG_CH) ses[t] = SE[(size_t)b * 512 + ch0 + t];

    for (int i = t; i < DG_TILE; i += 256) {
        int r = i / DG_TROW;
        int rem = i - r * DG_TROW;
        int x = rem >> 7, ch = rem & 127;
        int gy = y0 - 1 + r;
        float v1 = 0.f, v2 = 0.f;
        if (gy >= 0 && gy < 20) {
            size_t base = ((size_t)(b * NTOK + gy * 20 + x)) * 1024;
            v1 = __bfloat162float(Y[base + ch0 + ch]);
            v2 = __bfloat162float(Y[base + 512 + ch0 + ch]);
        }
        s1t[i] = v1; s2t[i] = v2;
    }
    __syncthreads();

    for (int oi = t; oi < 5 * DG_TROW; oi += 256) {
        int yl = oi / DG_TROW;
        int rem = oi - yl * DG_TROW;
        int x = rem >> 7, ch = rem & 127;
        float s1 = 0.f, s2 = 0.f;
#pragma unroll
        for (int ky = 0; ky < 3; ky++) {
            const float* r1 = s1t + (yl + ky) * DG_TROW + ch;
            const float* r2 = s2t + (yl + ky) * DG_TROW + ch;
            const float* ww1 = w1 + ch * 9 + ky * 3;
            const float* ww2 = w2 + ch * 9 + ky * 3;
#pragma unroll
            for (int kx = 0; kx < 3; kx++) {
                int xx = x + kx - 1;
                if (xx < 0 || xx >= 20) continue;
                s1 += r1[xx * DG_CH] * ww1[kx];
                s2 += r2[xx * DG_CH] * ww2[kx];
            }
        }
        float ge = 0.5f * s1 * (1.0f + erff(s1 * 0.70710678118654752f));
        int y = y0 + yl;
        Y2H[((size_t)(b * NTOK + y * 20 + x)) * 512 + ch0 + ch] =
            __float2bfloat16(ge * s2 * ses[ch]);
    }
}

// ---------------- launcher ----------------
extern "C" void kernel_launch(void* const* d_in, const int* in_sizes, int n_in,
                              void* d_out, int out_size) {
    const float* src    = (const float*)d_in[0];
    const float* qg_w   = (const float*)d_in[1];
    const float* qg_b   = (const float*)d_in[2];
    const float* kv_w   = (const float*)d_in[3];
    const float* kv_b   = (const float*)d_in[4];
    const float* proj_w = (const float*)d_in[5];
    const float* proj_b = (const float*)d_in[6];
    const float* dwc_w  = (const float*)d_in[7];
    const float* dwc_b  = (const float*)d_in[8];
    const float* power  = (const float*)d_in[9];
    const float* scale  = (const float*)d_in[10];
    const float* pos    = (const float*)d_in[11];
    const float* pin_w  = (const float*)d_in[12];
    const float* dw_w   = (const float*)d_in[13];
    const float* se_w   = (const float*)d_in[14];
    const float* pout_w = (const float*)d_in[15];
    const float* ln1_w  = (const float*)d_in[16];
    const float* ln1_b  = (const float*)d_in[17];
    const float* ln2_w  = (const float*)d_in[18];
    const float* ln2_b  = (const float*)d_in[19];
    float* out = (float*)d_out;

    float* scr = nullptr;
    cudaGetSymbolAddress((void**)&scr, d_scratch);

    float* XT   = scr + O_XT;
    __nv_bfloat16* XTH = (__nv_bfloat16*)(scr + O_XTH);
    __nv_bfloat16* G   = (__nv_bfloat16*)(scr + O_G);
    __nv_bfloat16* QP  = (__nv_bfloat16*)(scr + O_QP);
    __nv_bfloat16* QN  = (__nv_bfloat16*)(scr + O_QN);
    __nv_bfloat16* KP  = (__nv_bfloat16*)(scr + O_KP);
    __nv_bfloat16* KN  = (__nv_bfloat16*)(scr + O_KN);
    __nv_bfloat16* VF  = (__nv_bfloat16*)(scr + O_VF);
    __nv_bfloat16* VD  = (__nv_bfloat16*)(scr + O_VD);
    float* KM   = scr + O_KM;
    float* KVS  = scr + O_KVS;
    float* KVO  = scr + O_KVO;
    __nv_bfloat16* OUT2H = (__nv_bfloat16*)(scr + O_OUT2H);
    float* S    = scr + O_S;
    __nv_bfloat16* SH  = (__nv_bfloat16*)(scr + O_SH);
    __nv_bfloat16* YH  = (__nv_bfloat16*)(scr + O_YH);
    __nv_bfloat16* Y2H = (__nv_bfloat16*)(scr + O_Y2H);
    float* TMP  = scr + O_TMP;
    float* SE   = scr + O_SE;
    float* INV  = scr + O_INV;
    float* PW   = scr + O_PW;
    __nv_bfloat16* WPJH = (__nv_bfloat16*)(scr + O_WPJH);
    __nv_bfloat16* WPIH = (__nv_bfloat16*)(scr + O_WPIH);
    __nv_bfloat16* WPOH = (__nv_bfloat16*)(scr + O_WPOH);
    __nv_bfloat16* WQH  = (__nv_bfloat16*)(scr + O_WQH);
    __nv_bfloat16* WKH  = (__nv_bfloat16*)(scr + O_WKH);

    static bool attr_set = false;
    if (!attr_set) {
        cudaFuncSetAttribute(gemm_qgkv_bf, cudaFuncAttributeMaxDynamicSharedMemorySize, SMEM_GBF);
        cudaFuncSetAttribute(gemm_bf<true>, cudaFuncAttributeMaxDynamicSharedMemorySize, SMEM_GBF);
        cudaFuncSetAttribute(gemm_bf_ln<256,true>,  cudaFuncAttributeMaxDynamicSharedMemorySize, SMEM_GBLN);
        cudaFuncSetAttribute(gemm_bf_ln<512,false>, cudaFuncAttributeMaxDynamicSharedMemorySize, SMEM_GBLN);
        cudaFuncSetAttribute(k_dw_glu, cudaFuncAttributeMaxDynamicSharedMemorySize, SMEM_DG);
        attr_set = true;
    }

    // 1. weight conversion + param prep
    k_cvtw<<<256, 256>>>(proj_w, WPJH, 256*256, pin_w, WPIH, 1024*256,
                         pout_w, WPOH, 256*512, qg_w, WQH, 512*256, kv_w, WKH, 512*256,
                         scale, power, INV, PW);
    // 2. src -> token-major (fp32 + bf16)
    k_tr_src<<<dim3(13, 8, BATCH), dim3(32, 32)>>>(src, XT, XTH);
    // 3. merged qg + kv GEMMs (ldmatrix)
    gemm_qgkv_bf<<<dim3(4, 200, 2), 256, SMEM_GBF>>>(XTH, WQH, qg_b, WKH, kv_b,
        pos, INV, PW, QP, QN, G, KP, KN, VF);
    // 4. fused: reductions + dwc5x5 (row-streaming) + SE
    k_fused<<<1600, 256>>>(KP, KN, VF, KM, KVS, KVO, dwc_w, dwc_b, VD, src, se_w, SE);
    // 5. attention output + vd + gate -> bf16
    k_attn_out<<<512, 256>>>(QP, QN, KM, KVS, KVO, VD, G, OUT2H);
    // 6. proj + residual + LN1 -> S fp32 + SH bf16
    gemm_bf_ln<256,true><<<200, 512, SMEM_GBLN>>>(OUT2H, WPJH, proj_b, XT, ln1_w, ln1_b, S, SH);
    // 7. pin -> YH bf16
    gemm_bf<true><<<dim3(8, 200), 256, SMEM_GBF>>>(SH, WPIH, YH, TOKS, 1024, 256);
    // 8. dw3x3 + glu + se -> Y2H bf16
    k_dw_glu<<<dim3(4, 4, BATCH), 256, SMEM_DG>>>(YH, dw_w, SE, Y2H);
    // 9. pout + residual + LN2 -> TMP
    gemm_bf_ln<512,false><<<200, 512, SMEM_GBLN>>>(Y2H, WPOH, nullptr, S, ln2_w, ln2_b, TMP, nullptr);
    // 10. transpose to NCHW output
    k_tr_out<<<dim3(13, 8, BATCH), dim3(32, 32)>>>(TMP, out);
}

// round 17
// speedup vs baseline: 1.0407x; 1.0407x over previous
#include <cuda_runtime.h>
#include <cuda_bf16.h>
#include <math.h>
#include <stdint.h>

// ---------------- problem constants ----------------
#define BATCH 64
#define CCH   256
#define NTOK  400
#define TOKS  (BATCH*NTOK) // 25600

// ---------------- scratch layout (float units) ----------------
constexpr size_t O_XT    = 0;                          // fp32 TOKS*256
constexpr size_t O_XTH   = O_XT    + (size_t)TOKS*256; // bf16 TOKS*256
constexpr size_t O_G     = O_XTH   + (size_t)TOKS*128; // bf16 token-major
constexpr size_t O_QP    = O_G     + (size_t)TOKS*128; // bf16 token-major
constexpr size_t O_QN    = O_QP    + (size_t)TOKS*128;
constexpr size_t O_KP    = O_QN    + (size_t)TOKS*128;
constexpr size_t O_KN    = O_KP    + (size_t)TOKS*128;
constexpr size_t O_VF    = O_KN    + (size_t)TOKS*128; // bf16 flat
constexpr size_t O_VD    = O_VF    + (size_t)TOKS*128; // bf16 flat
constexpr size_t O_KM    = O_VD    + (size_t)TOKS*128;
constexpr size_t O_KVS   = O_KM    + (size_t)512*64;
constexpr size_t O_KVO   = O_KVS   + (size_t)512*1024;
constexpr size_t O_OUT2H = O_KVO   + (size_t)512*1024; // bf16 token-major
constexpr size_t O_S     = O_OUT2H + (size_t)TOKS*128; // fp32
constexpr size_t O_SH    = O_S     + (size_t)TOKS*256; // bf16
constexpr size_t O_YH    = O_SH    + (size_t)TOKS*128; // bf16 TOKS*1024
constexpr size_t O_Y2H   = O_YH    + (size_t)TOKS*512; // bf16 TOKS*512
constexpr size_t O_SE    = O_Y2H   + (size_t)TOKS*256;
constexpr size_t O_INV   = O_SE    + (size_t)BATCH*512;
constexpr size_t O_PW    = O_INV   + 256;
constexpr size_t O_WPJH  = O_PW    + 256;               // bf16 256*256
constexpr size_t O_WPIH  = O_WPJH  + 32768;             // bf16 1024*256
constexpr size_t O_WPOH  = O_WPIH  + 131072;            // bf16 256*512
constexpr size_t O_WQH   = O_WPOH  + 65536;             // bf16 512*256
constexpr size_t O_WKH   = O_WQH   + 65536;             // bf16 512*256
constexpr size_t SCR_TOTAL = O_WKH + 65536;

__device__ __align__(256) float d_scratch[SCR_TOTAL];

// =======================================================================
// helpers
// =======================================================================
__device__ __forceinline__ uint32_t smem_u32(const void* p) {
    uint32_t a;
    asm("{ .reg .u64 t; cvta.to.shared.u64 t, %1; cvt.u32.u64 %0, t; }" : "=r"(a) : "l"(p));
    return a;
}
__device__ __forceinline__ void cp16(uint32_t s, const void* g) {
    asm volatile("cp.async.ca.shared.global [%0], [%1], 16;" :: "r"(s), "l"(g));
}
#define CP_COMMIT() asm volatile("cp.async.commit_group;" ::: "memory")
#define CP_WAIT(n)  asm volatile("cp.async.wait_group %0;" :: "n"(n) : "memory")

__device__ __forceinline__ void mma_bf16(float* d, const uint32_t* a, const uint32_t* b) {
    asm volatile(
        "mma.sync.aligned.m16n8k16.row.col.f32.bf16.bf16.f32 "
        "{%0,%1,%2,%3}, {%4,%5,%6,%7}, {%8,%9}, {%0,%1,%2,%3};"
        : "+f"(d[0]), "+f"(d[1]), "+f"(d[2]), "+f"(d[3])
        : "r"(a[0]), "r"(a[1]), "r"(a[2]), "r"(a[3]), "r"(b[0]), "r"(b[1]));
}
__device__ __forceinline__ void ldm_x4(uint32_t* r, uint32_t addr) {
    asm volatile("ldmatrix.sync.aligned.m8n8.x4.shared.b16 {%0,%1,%2,%3}, [%4];"
        : "=r"(r[0]), "=r"(r[1]), "=r"(r[2]), "=r"(r[3]) : "r"(addr));
}
__device__ __forceinline__ void ldm_x2(uint32_t* r, uint32_t addr) {
    asm volatile("ldmatrix.sync.aligned.m8n8.x2.shared.b16 {%0,%1}, [%2];"
        : "=r"(r[0]), "=r"(r[1]) : "r"(addr));
}

constexpr int HROWB = 144;                 // bytes per smem row (64 bf16 + pad)
constexpr int HB_TILE_B = 128 * HROWB;     // 18432
constexpr int HB_STAGE  = 2 * HB_TILE_B;   // 36864
constexpr int SMEM_GBF  = 3 * HB_STAGE;    // 110592 (3-stage)

// =======================================================================
// gemm_qgkv_bf: merged qg + kv GEMMs. grid (4, 200, 2). 3-stage, ldmatrix.
// =======================================================================
__global__ __launch_bounds__(256, 2)
void gemm_qgkv_bf(const __nv_bfloat16* __restrict__ A,
                  const __nv_bfloat16* __restrict__ wq, const float* __restrict__ bq,
                  const __nv_bfloat16* __restrict__ wk, const float* __restrict__ bk,
                  const float* __restrict__ pos,
                  const float* __restrict__ invsc, const float* __restrict__ pw,
                  __nv_bfloat16* __restrict__ QP, __nv_bfloat16* __restrict__ QN,
                  __nv_bfloat16* __restrict__ G,
                  __nv_bfloat16* __restrict__ KP, __nv_bfloat16* __restrict__ KN,
                  __nv_bfloat16* __restrict__ VF) {
    const int K = 256;
    extern __shared__ float sm[];
    const uint32_t sbase = smem_u32(sm);
    const int t = threadIdx.x, lane = t & 31, wid = t >> 5;
    const int wm = (wid >> 2) * 64;
    const int wn = (wid & 3) * 32;
    const int bm = blockIdx.y * 128, bn = blockIdx.x * 128;
    const int g4 = lane >> 2, l4 = lane & 3;
    const bool isKV = (blockIdx.z != 0);
    const __nv_bfloat16* Bw = isKV ? wk : wq;
    const float* bias = isKV ? bk : bq;

    const uint32_t a_lo = (uint32_t)((wm + (lane & 7) + ((lane >> 3) & 1) * 8) * HROWB
                                     + ((lane >> 4) & 1) * 16);
    const int lbi = lane & 15;
    const uint32_t b_lo = (uint32_t)((wn + (lbi & 7)) * HROWB + ((lbi >> 3) & 1) * 16);

    auto load_chunk = [&](int ch, int buf) {
        int k0 = ch << 6;
        uint32_t sb = sbase + (uint32_t)buf * HB_STAGE;
#pragma unroll
        for (int i = 0; i < 8; i++) {
            int o = t + i * 256;
            int isB = o >> 10;
            int row = (o & 1023) >> 3;
            int seg = o & 7;
            const __nv_bfloat16* g = (isB ? Bw + (size_t)(bn + row) * K
                                          : A  + (size_t)(bm + row) * K) + k0 + seg * 8;
            uint32_t s = sb + (uint32_t)(isB * HB_TILE_B + row * HROWB + seg * 16);
            cp16(s, g);
        }
        CP_COMMIT();
    };

    float acc[4][4][4];
#pragma unroll
    for (int mi = 0; mi < 4; mi++)
#pragma unroll
        for (int ni = 0; ni < 4; ni++)
#pragma unroll
            for (int k = 0; k < 4; k++) acc[mi][ni][k] = 0.0f;

    const int NC = 4;
    load_chunk(0, 0);
    load_chunk(1, 1);
    for (int ch = 0; ch < NC; ch++) {
        if (ch == NC - 1) { CP_WAIT(0); } else { CP_WAIT(1); }
        __syncthreads();
        if (ch + 2 < NC) load_chunk(ch + 2, (ch + 2) % 3);
        uint32_t Ab = sbase + (uint32_t)((ch % 3) * HB_STAGE);
        uint32_t Bb = Ab + HB_TILE_B;
#pragma unroll
        for (int s = 0; s < 4; s++) {
            uint32_t ah[4][4], bh[4][2];
#pragma unroll
            for (int mi = 0; mi < 4; mi++)
                ldm_x4(ah[mi], Ab + a_lo + (uint32_t)(mi * 16 * HROWB + s * 32));
#pragma unroll
            for (int ni = 0; ni < 4; ni++)
                ldm_x2(bh[ni], Bb + b_lo + (uint32_t)(ni * 8 * HROWB + s * 32));
#pragma unroll
            for (int mi = 0; mi < 4; mi++)
#pragma unroll
                for (int ni = 0; ni < 4; ni++)
                    mma_bf16(acc[mi][ni], ah[mi], bh[ni]);
        }
    }

    bool first_half = (bn < 256);
#pragma unroll
    for (int mi = 0; mi < 4; mi++) {
#pragma unroll
        for (int half = 0; half < 2; half++) {
            int r = bm + wm + mi * 16 + g4 + half * 8;
            int tok = r % NTOK;
#pragma unroll
            for (int ni = 0; ni < 4; ni++) {
                int cb = bn + wn + ni * 8 + 2 * l4;
                float v0 = acc[mi][ni][half * 2 + 0] + bias[cb];
                float v1 = acc[mi][ni][half * 2 + 1] + bias[cb + 1];
                if (first_half) {
                    float xp0 = 0.f, xn0 = 0.f, xp1 = 0.f, xn1 = 0.f;
#pragma unroll
                    for (int j = 0; j < 2; j++) {
                        int ccol = cb + j;
                        float v = j ? v1 : v0;
                        float x = isKV ? (v + pos[(size_t)tok * 256 + ccol]) * invsc[ccol]
                                       : v * invsc[ccol];
                        float p = pw[ccol];
                        float xp = 0.f, xn = 0.f;
                        if (x > 0.f)      xp = __powf(fmaxf(x, 1e-30f), p);
                        else if (x < 0.f) xn = __powf(fmaxf(-x, 1e-30f), p);
                        if (j) { xp1 = xp; xn1 = xn; } else { xp0 = xp; xn0 = xn; }
                    }
                    __nv_bfloat16* P1 = isKV ? KP : QP;
                    __nv_bfloat16* P2 = isKV ? KN : QN;
                    *(__nv_bfloat162*)&P1[(size_t)r * 256 + cb] =
                        __floats2bfloat162_rn(xp0, xp1);
                    *(__nv_bfloat162*)&P2[(size_t)r * 256 + cb] =
                        __floats2bfloat162_rn(xn0, xn1);
                } else {
                    int cc = cb - 256;
                    __nv_bfloat16* P3 = isKV ? VF : G;
                    *(__nv_bfloat162*)&P3[(size_t)r * 256 + cc] =
                        __floats2bfloat162_rn(v0, v1);
                }
            }
        }
    }
}

// =======================================================================
// gemm_bf: bf16 GEMM, 3-stage, ldmatrix. OB: bf16 output.
// =======================================================================
template<bool OB>
__global__ __launch_bounds__(256, 2)
void gemm_bf(const __nv_bfloat16* __restrict__ A, const __nv_bfloat16* __restrict__ Bw,
             void* __restrict__ Cv, int M, int N, int K) {
    extern __shared__ float sm[];
    const uint32_t sbase = smem_u32(sm);
    const int t = threadIdx.x, lane = t & 31, wid = t >> 5;
    const int wm = (wid >> 2) * 64;
    const int wn = (wid & 3) * 32;
    const int bm = blockIdx.y * 128, bn = blockIdx.x * 128;
    const int g4 = lane >> 2, l4 = lane & 3;
    const int NC = K >> 6;

    const uint32_t a_lo = (uint32_t)((wm + (lane & 7) + ((lane >> 3) & 1) * 8) * HROWB
                                     + ((lane >> 4) & 1) * 16);
    const int lbi = lane & 15;
    const uint32_t b_lo = (uint32_t)((wn + (lbi & 7)) * HROWB + ((lbi >> 3) & 1) * 16);

    auto load_chunk = [&](int ch, int buf) {
        int k0 = ch << 6;
        uint32_t sb = sbase + (uint32_t)buf * HB_STAGE;
#pragma unroll
        for (int i = 0; i < 8; i++) {
            int o = t + i * 256;
            int isB = o >> 10;
            int row = (o & 1023) >> 3;
            int seg = o & 7;
            const __nv_bfloat16* g = (isB ? Bw + (size_t)(bn + row) * K
                                          : A  + (size_t)(bm + row) * K) + k0 + seg * 8;
            uint32_t s = sb + (uint32_t)(isB * HB_TILE_B + row * HROWB + seg * 16);
            cp16(s, g);
        }
        CP_COMMIT();
    };

    float acc[4][4][4];
#pragma unroll
    for (int mi = 0; mi < 4; mi++)
#pragma unroll
        for (int ni = 0; ni < 4; ni++)
#pragma unroll
            for (int k = 0; k < 4; k++) acc[mi][ni][k] = 0.0f;

    load_chunk(0, 0);
    if (NC > 1) load_chunk(1, 1);

    for (int ch = 0; ch < NC; ch++) {
        if (ch == NC - 1) { CP_WAIT(0); } else { CP_WAIT(1); }
        __syncthreads();
        if (ch + 2 < NC) load_chunk(ch + 2, (ch + 2) % 3);
        uint32_t Ab = sbase + (uint32_t)((ch % 3) * HB_STAGE);
        uint32_t Bb = Ab + HB_TILE_B;
#pragma unroll
        for (int s = 0; s < 4; s++) {
            uint32_t ah[4][4], bh[4][2];
#pragma unroll
            for (int mi = 0; mi < 4; mi++)
                ldm_x4(ah[mi], Ab + a_lo + (uint32_t)(mi * 16 * HROWB + s * 32));
#pragma unroll
            for (int ni = 0; ni < 4; ni++)
                ldm_x2(bh[ni], Bb + b_lo + (uint32_t)(ni * 8 * HROWB + s * 32));
#pragma unroll
            for (int mi = 0; mi < 4; mi++)
#pragma unroll
                for (int ni = 0; ni < 4; ni++)
                    mma_bf16(acc[mi][ni], ah[mi], bh[ni]);
        }
    }

#pragma unroll
    for (int mi = 0; mi < 4; mi++) {
        int r0 = bm + wm + mi * 16 + g4;
#pragma unroll
        for (int ni = 0; ni < 4; ni++) {
            int cb = bn + wn + ni * 8 + 2 * l4;
            if (OB) {
                __nv_bfloat16* C = (__nv_bfloat16*)Cv;
                *(__nv_bfloat162*)&C[(size_t)r0 * N + cb] =
                    __floats2bfloat162_rn(acc[mi][ni][0], acc[mi][ni][1]);
                *(__nv_bfloat162*)&C[(size_t)(r0 + 8) * N + cb] =
                    __floats2bfloat162_rn(acc[mi][ni][2], acc[mi][ni][3]);
            } else {
                float* C = (float*)Cv;
                *(float2*)&C[(size_t)r0 * N + cb]       = make_float2(acc[mi][ni][0], acc[mi][ni][1]);
                *(float2*)&C[(size_t)(r0 + 8) * N + cb] = make_float2(acc[mi][ni][2], acc[mi][ni][3]);
            }
        }
    }
}

// =======================================================================
// gemm_bf_ln: OUT = LN( RES + A@Bw^T (+bias) ), N=256, 512 thr, 2-stage, ldmatrix.
// TROUT: write OUT in NCHW layout (b, c, n) instead of token-major.
// =======================================================================
constexpr int HL_TA_B  = 128 * HROWB;
constexpr int HL_STAGE = (128 + 256) * HROWB;   // 55296
constexpr int SMEM_GBLN = 2 * HL_STAGE;         // 110592

template<int KD, bool WH, bool TROUT>
__global__ __launch_bounds__(512)
void gemm_bf_ln(const __nv_bfloat16* __restrict__ A, const __nv_bfloat16* __restrict__ Bw,
                const float* __restrict__ bias, const float* __restrict__ RES,
                const float* __restrict__ lw, const float* __restrict__ lb,
                float* __restrict__ OUT, __nv_bfloat16* __restrict__ OUTH) {
    const int N = 256;
    extern __shared__ float sm[];
    const uint32_t sbase = smem_u32(sm);
    const int t = threadIdx.x, lane = t & 31, wid = t >> 5;
    const int wm = (wid >> 2) * 32;
    const int wn = (wid & 3) * 64;
    const int bm = blockIdx.x * 128;
    const int g4 = lane >> 2, l4 = lane & 3;
    const int NC = KD >> 6;

    const uint32_t a_lo = (uint32_t)((wm + (lane & 7) + ((lane >> 3) & 1) * 8) * HROWB
                                     + ((lane >> 4) & 1) * 16);
    const int lbi = lane & 15;
    const uint32_t b_lo = (uint32_t)((wn + (lbi & 7)) * HROWB + ((lbi >> 3) & 1) * 16);

    auto load_chunk = [&](int ch, int buf) {
        int k0 = ch << 6;
        uint32_t sb = sbase + (uint32_t)buf * HL_STAGE;
#pragma unroll
        for (int i = 0; i < 6; i++) {
            int o = t + i * 512;
            bool isB = o >= 1024;
            int row = isB ? ((o - 1024) >> 3) : (o >> 3);
            int seg = o & 7;
            const __nv_bfloat16* g = (isB ? Bw + (size_t)row * KD
                                          : A  + (size_t)(bm + row) * KD) + k0 + seg * 8;
            uint32_t s = sb + (uint32_t)((isB ? HL_TA_B : 0) + row * HROWB + seg * 16);
            cp16(s, g);
        }
        CP_COMMIT();
    };

    float acc[2][8][4];
#pragma unroll
    for (int mi = 0; mi < 2; mi++)
#pragma unroll
        for (int ni = 0; ni < 8; ni++)
#pragma unroll
            for (int k = 0; k < 4; k++) acc[mi][ni][k] = 0.0f;

    load_chunk(0, 0);
    if (NC > 1) load_chunk(1, 1);

    for (int ch = 0; ch < NC; ch++) {
        if (ch + 1 < NC) { CP_WAIT(1); } else { CP_WAIT(0); }
        __syncthreads();
        uint32_t Ab = sbase + (uint32_t)((ch & 1) * HL_STAGE);
        uint32_t Bb = Ab + HL_TA_B;
#pragma unroll
        for (int s = 0; s < 4; s++) {
            uint32_t af[2][4], bf[8][2];
#pragma unroll
            for (int mi = 0; mi < 2; mi++)
                ldm_x4(af[mi], Ab + a_lo + (uint32_t)(mi * 16 * HROWB + s * 32));
#pragma unroll
            for (int ni = 0; ni < 8; ni++)
                ldm_x2(bf[ni], Bb + b_lo + (uint32_t)(ni * 8 * HROWB + s * 32));
#pragma unroll
            for (int mi = 0; mi < 2; mi++)
#pragma unroll
                for (int ni = 0; ni < 8; ni++)
                    mma_bf16(acc[mi][ni], af[mi], bf[ni]);
        }
        __syncthreads();
        if (ch + 2 < NC) load_chunk(ch + 2, ch & 1);
    }

    __syncthreads();
    float* ssum = sm;
    float* ssq  = sm + 512;

#pragma unroll
    for (int mi = 0; mi < 2; mi++)
#pragma unroll
        for (int half = 0; half < 2; half++) {
            int r = bm + wm + mi * 16 + g4 + half * 8;
#pragma unroll
            for (int ni = 0; ni < 8; ni++)
#pragma unroll
                for (int j = 0; j < 2; j++) {
                    int c = wn + ni * 8 + 2 * l4 + j;
                    float b = bias ? bias[c] : 0.f;
                    acc[mi][ni][half * 2 + j] += b + RES[(size_t)r * N + c];
                }
        }
#pragma unroll
    for (int mi = 0; mi < 2; mi++)
#pragma unroll
        for (int half = 0; half < 2; half++) {
            float s = 0.f, q = 0.f;
#pragma unroll
            for (int ni = 0; ni < 8; ni++)
#pragma unroll
                for (int j = 0; j < 2; j++) {
                    float v = acc[mi][ni][half * 2 + j];
                    s += v; q += v * v;
                }
            s += __shfl_xor_sync(0xffffffffu, s, 1);
            s += __shfl_xor_sync(0xffffffffu, s, 2);
            q += __shfl_xor_sync(0xffffffffu, q, 1);
            q += __shfl_xor_sync(0xffffffffu, q, 2);
            if (l4 == 0) {
                int lr = wm + mi * 16 + g4 + half * 8;
                ssum[(wid & 3) * 128 + lr] = s;
                ssq[(wid & 3) * 128 + lr]  = q;
            }
        }
    __syncthreads();
#pragma unroll
    for (int mi = 0; mi < 2; mi++)
#pragma unroll
        for (int half = 0; half < 2; half++) {
            int lr = wm + mi * 16 + g4 + half * 8;
            float s = ssum[lr] + ssum[128 + lr] + ssum[256 + lr] + ssum[384 + lr];
            float q = ssq[lr]  + ssq[128 + lr]  + ssq[256 + lr]  + ssq[384 + lr];
            float mean = s * (1.0f / 256.0f);
            float var  = q * (1.0f / 256.0f) - mean * mean;
            float inv  = rsqrtf(var + 1e-6f);
            int r = bm + lr;
            int bb = r / NTOK;
            int n  = r - bb * NTOK;
#pragma unroll
            for (int ni = 0; ni < 8; ni++)
#pragma unroll
                for (int j = 0; j < 2; j++) {
                    int c = wn + ni * 8 + 2 * l4 + j;
                    float v = acc[mi][ni][half * 2 + j];
                    float o = lw[c] * (v - mean) * inv + lb[c];
                    if (TROUT) {
                        OUT[(size_t)bb * (CCH * NTOK) + (size_t)c * NTOK + n] = o;
                    } else {
                        OUT[(size_t)r * N + c] = o;
                    }
                    if (WH) OUTH[(size_t)r * N + c] = __float2bfloat16(o);
                }
        }
}

// ---------------- weight -> bf16 convert + param prep ----------------
__global__ void k_cvtw(const float* __restrict__ p1, __nv_bfloat16* __restrict__ o1, int n1,
                       const float* __restrict__ p2, __nv_bfloat16* __restrict__ o2, int n2,
                       const float* __restrict__ p3, __nv_bfloat16* __restrict__ o3, int n3,
                       const float* __restrict__ p4, __nv_bfloat16* __restrict__ o4, int n4,
                       const float* __restrict__ p5, __nv_bfloat16* __restrict__ o5, int n5,
                       const float* __restrict__ scale, const float* __restrict__ power,
                       float* __restrict__ invsc, float* __restrict__ pw) {
    if (blockIdx.x == 0 && threadIdx.x < 256) {
        int c = threadIdx.x;
        float sp = log1pf(expf(scale[c]));
        invsc[c] = 1.0f / sp;
        pw[c] = 1.0f + 4.0f / (1.0f + expf(-power[c]));
    }
    int total = n1 + n2 + n3 + n4 + n5;
    for (int i = blockIdx.x * blockDim.x + threadIdx.x; i < total; i += gridDim.x * blockDim.x) {
        int r = i;
        if (r < n1) { o1[r] = __float2bfloat16(p1[r]); continue; } r -= n1;
        if (r < n2) { o2[r] = __float2bfloat16(p2[r]); continue; } r -= n2;
        if (r < n3) { o3[r] = __float2bfloat16(p3[r]); continue; } r -= n3;
        if (r < n4) { o4[r] = __float2bfloat16(p4[r]); continue; } r -= n4;
        o5[r] = __float2bfloat16(p5[r]);
    }
}

// ---------------- transpose (B,C,400) -> (B,400,C) fp32 + bf16 ----------------
__global__ void k_tr_src(const float* __restrict__ src, float* __restrict__ XT,
                         __nv_bfloat16* __restrict__ XTH) {
    __shared__ float tile[32][33];
    int b = blockIdx.z, cb = blockIdx.y * 32, nb = blockIdx.x * 32;
    int tx = threadIdx.x, ty = threadIdx.y;
    int n = nb + tx, c = cb + ty;
    if (n < NTOK) tile[ty][tx] = src[(size_t)b*CCH*NTOK + (size_t)c*NTOK + n];
    __syncthreads();
    n = nb + ty; c = cb + tx;
    if (n < NTOK) {
        float v = tile[tx][ty];
        size_t o = ((size_t)b*NTOK + n)*CCH + c;
        XT[o] = v;
        XTH[o] = __float2bfloat16(v);
    }
}

// =======================================================================
// k_fused: [0,512) reductions (80-token chunks);
//          [512,1536) dwc5x5 (weights in regs, 25 LDS/out — R15 form);
//          [1536,1600) SE
// =======================================================================
__global__ __launch_bounds__(256)
void k_fused(const __nv_bfloat16* __restrict__ KP, const __nv_bfloat16* __restrict__ KN,
             const __nv_bfloat16* __restrict__ VF,
             float* __restrict__ KM, float* __restrict__ KVS, float* __restrict__ KVO,
             const float* __restrict__ dwcw, const float* __restrict__ dwcb,
             __nv_bfloat16* __restrict__ VD,
             const float* __restrict__ src, const float* __restrict__ sew,
             float* __restrict__ SE) {
    __shared__ float fsm[14*640];
    int bid = blockIdx.x;
    int t = threadIdx.x;

    if (bid < 512) {
        float* kc_s = fsm;            // [80][64]
        float* v_s  = fsm + 5120;     // [80][32]
        int bh = bid, b = bh >> 3, h = bh & 7;
        int j = t >> 2, e0 = (t & 3) << 2;
        float accs[4] = {0,0,0,0}, acco[4] = {0,0,0,0}, accm = 0.f;
        for (int n0 = 0; n0 < NTOK; n0 += 80) {
#pragma unroll
            for (int rr = 0; rr < 10; rr++) {
                int idx = t + rr * 256;
                int nl = idx >> 5, j2 = idx & 31;
                size_t row = ((size_t)(b*NTOK + n0 + nl))*256 + h*32;
                __nv_bfloat162 pr = (j2 < 16)
                    ? *(const __nv_bfloat162*)&KP[row + 2*j2]
                    : *(const __nv_bfloat162*)&KN[row + 2*(j2-16)];
                float2 f = __bfloat1622float2(pr);
                *(float2*)&kc_s[nl*64 + 2*j2] = f;
            }
#pragma unroll
            for (int rr = 0; rr < 5; rr++) {
                int idx = t + rr * 256;
                int nl = idx >> 4, e2 = idx & 15;
                int ee = 2*e2;
                size_t row = ((size_t)(b*NTOK + n0 + nl))*256;
                size_t base = (ee < 16) ? row + h*16 + ee : row + 128 + h*16 + (ee-16);
                float2 f = __bfloat1622float2(*(const __nv_bfloat162*)&VF[base]);
                *(float2*)&v_s[nl*32 + ee] = f;
            }
            __syncthreads();
#pragma unroll 4
            for (int nl = 0; nl < 80; nl++) {
                float kcv = kc_s[nl*64 + j];
                accm += kcv;
                float4 vs = *(const float4*)&v_s[nl*32 + e0];
                float4 vo = *(const float4*)&v_s[nl*32 + 16 + e0];
                accs[0] += kcv*vs.x; accs[1] += kcv*vs.y;
                accs[2] += kcv*vs.z; accs[3] += kcv*vs.w;
                acco[0] += kcv*vo.x; acco[1] += kcv*vo.y;
                acco[2] += kcv*vo.z; acco[3] += kcv*vo.w;
            }
            __syncthreads();
        }
        const float invN = 1.0f / (float)NTOK;
        size_t ob = (size_t)bh*1024 + (size_t)j*16 + e0;
#pragma unroll
        for (int q = 0; q < 4; q++) { KVS[ob+q] = accs[q]*invN; KVO[ob+q] = acco[q]*invN; }
        if ((t & 3) == 0) KM[(size_t)bh*64 + j] = accm * invN;
    } else if (bid < 1536) {
        float* tile = fsm;
        int blk = bid - 512;
        int half = blk & 1, g = (blk >> 1) & 7, b = blk >> 4;
        int dd = t & 31;
        float wreg[25];
#pragma unroll
        for (int k = 0; k < 25; k++) wreg[k] = dwcw[dd*25 + k];
        float bsv = dwcb[dd];
        const __nv_bfloat16* Vb = VF + (size_t)b*102400 + (size_t)g*12800;
        int r0 = half*10 - 2;
        for (int i = t; i < 14*80; i += 256) {
            int rr = i / 80, seg = i - rr*80;
            int r = r0 + rr;
            float4 f0 = make_float4(0,0,0,0), f1 = make_float4(0,0,0,0);
            if (r >= 0 && r < 20) {
                uint4 u = *(const uint4*)(Vb + r*640 + seg*8);
                float2 q0 = __bfloat1622float2(*(__nv_bfloat162*)&u.x);
                float2 q1 = __bfloat1622float2(*(__nv_bfloat162*)&u.y);
                float2 q2 = __bfloat1622float2(*(__nv_bfloat162*)&u.z);
                float2 q3 = __bfloat1622float2(*(__nv_bfloat162*)&u.w);
                f0 = make_float4(q0.x, q0.y, q1.x, q1.y);
                f1 = make_float4(q2.x, q2.y, q3.x, q3.y);
            }
            *(float4*)&tile[rr*640 + seg*8]     = f0;
            *(float4*)&tile[rr*640 + seg*8 + 4] = f1;
        }
        __syncthreads();
        for (int oi = t; oi < 10*640; oi += 256) {
            int yl = oi / 640, rem = oi - yl*640;
            int x = rem >> 5;
            float acc = bsv;
#pragma unroll
            for (int ky = 0; ky < 5; ky++) {
                const float* tr = tile + (yl + ky)*640 + dd;
#pragma unroll
                for (int kx = 0; kx < 5; kx++) {
                    int xx = x + kx - 2;
                    if (xx >= 0 && xx < 20)
                        acc += tr[xx*32] * wreg[ky*5 + kx];
                }
            }
            int y = half*10 + yl;
            VD[(size_t)b*102400 + (size_t)g*12800 + (size_t)y*640 + rem] =
                __float2bfloat16(acc);
        }
    } else {
        float* smv = fsm;
        int b = bid - 1536;
        int w = t >> 5, lane = t & 31;
        for (int ci = 0; ci < 32; ci++) {
            int c = w*32 + ci;
            const float* p = src + (size_t)b*102400 + (size_t)c*400;
            float s = 0.f;
            for (int n = lane; n < 400; n += 32) s += p[n];
#pragma unroll
            for (int off = 16; off; off >>= 1) s += __shfl_xor_sync(0xffffffffu, s, off);
            if (lane == 0) smv[c] = s * (1.0f/400.0f);
        }
        __syncthreads();
        for (int o = t; o < 512; o += 256) {
            const float4* wr = (const float4*)(sew + (size_t)o*256);
            float acc = 0.f;
#pragma unroll 8
            for (int c4 = 0; c4 < 64; c4++) {
                float4 w4 = wr[c4];
                float4 s4 = *(const float4*)&smv[c4*4];
                acc += w4.x*s4.x + w4.y*s4.y + w4.z*s4.z + w4.w*s4.w;
            }
            SE[(size_t)b*512 + o] = 1.0f / (1.0f + expf(-acc));
        }
    }
}

// ---------------- attention output + vd + gate ----------------
__global__ __launch_bounds__(256)
void k_attn_out(const __nv_bfloat16* __restrict__ QP, const __nv_bfloat16* __restrict__ QN,
                const float* __restrict__ KM, const float* __restrict__ KVS,
                const float* __restrict__ KVO, const __nv_bfloat16* __restrict__ VD,
                const __nv_bfloat16* __restrict__ G, __nv_bfloat16* __restrict__ OUT2H) {
    int bh = blockIdx.x, b = bh >> 3, h = bh & 7;
    __shared__ float km_s[64];
    __shared__ float kvb[64][32];
    __shared__ float qps[8][32], qns[8][32];
    int t = threadIdx.x, w = t >> 5, d = t & 31;
    for (int idx = t; idx < 64; idx += 256) km_s[idx] = KM[(size_t)bh*64 + idx];
    for (int idx = t; idx < 2048; idx += 256) {
        int j = idx >> 5, col = idx & 31;
        kvb[j][col] = (col < 16) ? KVS[(size_t)bh*1024 + j*16 + col]
                                 : KVO[(size_t)bh*1024 + j*16 + (col - 16)];
    }
    __syncthreads();
    bool sim = (d < 16);
    for (int n0 = 0; n0 < NTOK; n0 += 8) {
        int n = n0 + w;
        size_t tokbase = ((size_t)(b*NTOK + n)) * 256;
        float qp = __bfloat162float(QP[tokbase + h*32 + d]);
        float qn = __bfloat162float(QN[tokbase + h*32 + d]);
        qps[w][d] = qp; qns[w][d] = qn;
        __syncwarp();
        float d1 = qp*km_s[d] + qn*km_s[32 + d];
        float d2 = qn*km_s[d] + qp*km_s[32 + d];
#pragma unroll
        for (int off = 16; off; off >>= 1) {
            d1 += __shfl_xor_sync(0xffffffffu, d1, off);
            d2 += __shfl_xor_sync(0xffffffffu, d2, off);
        }
        float acc = 0.f;
#pragma unroll
        for (int j = 0; j < 32; j++) {
            float a = qps[w][j], bb = qns[w][j];
            float m1 = sim ? a : bb;
            float m2 = sim ? bb : a;
            acc += m1*kvb[j][d] + m2*kvb[32 + j][d];
        }
        float den = (sim ? d1 : d2) + 1e-6f;
        float val = acc / den;
        int c = h*32 + d;
        float vdv = __bfloat162float(VD[tokbase + c]);
        float gg  = __bfloat162float(G[tokbase + c]);
        OUT2H[tokbase + c] = __float2bfloat16((val + vdv) * gg);
        __syncwarp();
    }
}

// ---------------- dw3x3 + GLU(gelu) + SE scale — SMEM tiled ----------------
constexpr int DG_CH  = 128;
constexpr int DG_TROW = 20 * DG_CH;
constexpr int DG_TILE = 7 * DG_TROW;
constexpr int SMEM_DG = (2 * DG_TILE + 2 * DG_CH * 9 + DG_CH) * 4;

__global__ __launch_bounds__(256)
void k_dw_glu(const __nv_bfloat16* __restrict__ Y, const float* __restrict__ dww,
              const float* __restrict__ SE, __nv_bfloat16* __restrict__ Y2H) {
    extern __shared__ float dsm[];
    float* s1t = dsm;
    float* s2t = dsm + DG_TILE;
    float* w1  = dsm + 2 * DG_TILE;
    float* w2  = w1 + DG_CH * 9;
    float* ses = w2 + DG_CH * 9;

    int cq = blockIdx.x, ys = blockIdx.y, b = blockIdx.z;
    int t = threadIdx.x;
    int ch0 = cq * DG_CH;
    int y0 = ys * 5;

    for (int i = t; i < DG_CH * 9; i += 256) {
        int ch = i / 9, k = i % 9;
        w1[i] = dww[(ch0 + ch) * 9 + k];
        w2[i] = dww[(512 + ch0 + ch) * 9 + k];
    }
    if (t < DG_CH) ses[t] = SE[(size_t)b * 512 + ch0 + t];

    for (int i = t; i < DG_TILE; i += 256) {
        int r = i / DG_TROW;
        int rem = i - r * DG_TROW;
        int x = rem >> 7, ch = rem & 127;
        int gy = y0 - 1 + r;
        float v1 = 0.f, v2 = 0.f;
        if (gy >= 0 && gy < 20) {
            size_t base = ((size_t)(b * NTOK + gy * 20 + x)) * 1024;
            v1 = __bfloat162float(Y[base + ch0 + ch]);
            v2 = __bfloat162float(Y[base + 512 + ch0 + ch]);
        }
        s1t[i] = v1; s2t[i] = v2;
    }
    __syncthreads();

    for (int oi = t; oi < 5 * DG_TROW; oi += 256) {
        int yl = oi / DG_TROW;
        int rem = oi - yl * DG_TROW;
        int x = rem >> 7, ch = rem & 127;
        float s1 = 0.f, s2 = 0.f;
#pragma unroll
        for (int ky = 0; ky < 3; ky++) {
            const float* r1 = s1t + (yl + ky) * DG_TROW + ch;
            const float* r2 = s2t + (yl + ky) * DG_TROW + ch;
            const float* ww1 = w1 + ch * 9 + ky * 3;
            const float* ww2 = w2 + ch * 9 + ky * 3;
#pragma unroll
            for (int kx = 0; kx < 3; kx++) {
                int xx = x + kx - 1;
                if (xx < 0 || xx >= 20) continue;
                s1 += r1[xx * DG_CH] * ww1[kx];
                s2 += r2[xx * DG_CH] * ww2[kx];
            }
        }
        float ge = 0.5f * s1 * (1.0f + erff(s1 * 0.70710678118654752f));
        int y = y0 + yl;
        Y2H[((size_t)(b * NTOK + y * 20 + x)) * 512 + ch0 + ch] =
            __float2bfloat16(ge * s2 * ses[ch]);
    }
}

// ---------------- launcher ----------------
extern "C" void kernel_launch(void* const* d_in, const int* in_sizes, int n_in,
                              void* d_out, int out_size) {
    const float* src    = (const float*)d_in[0];
    const float* qg_w   = (const float*)d_in[1];
    const float* qg_b   = (const float*)d_in[2];
    const float* kv_w   = (const float*)d_in[3];
    const float* kv_b   = (const float*)d_in[4];
    const float* proj_w = (const float*)d_in[5];
    const float* proj_b = (const float*)d_in[6];
    const float* dwc_w  = (const float*)d_in[7];
    const float* dwc_b  = (const float*)d_in[8];
    const float* power  = (const float*)d_in[9];
    const float* scale  = (const float*)d_in[10];
    const float* pos    = (const float*)d_in[11];
    const float* pin_w  = (const float*)d_in[12];
    const float* dw_w   = (const float*)d_in[13];
    const float* se_w   = (const float*)d_in[14];
    const float* pout_w = (const float*)d_in[15];
    const float* ln1_w  = (const float*)d_in[16];
    const float* ln1_b  = (const float*)d_in[17];
    const float* ln2_w  = (const float*)d_in[18];
    const float* ln2_b  = (const float*)d_in[19];
    float* out = (float*)d_out;

    float* scr = nullptr;
    cudaGetSymbolAddress((void**)&scr, d_scratch);

    float* XT   = scr + O_XT;
    __nv_bfloat16* XTH = (__nv_bfloat16*)(scr + O_XTH);
    __nv_bfloat16* G   = (__nv_bfloat16*)(scr + O_G);
    __nv_bfloat16* QP  = (__nv_bfloat16*)(scr + O_QP);
    __nv_bfloat16* QN  = (__nv_bfloat16*)(scr + O_QN);
    __nv_bfloat16* KP  = (__nv_bfloat16*)(scr + O_KP);
    __nv_bfloat16* KN  = (__nv_bfloat16*)(scr + O_KN);
    __nv_bfloat16* VF  = (__nv_bfloat16*)(scr + O_VF);
    __nv_bfloat16* VD  = (__nv_bfloat16*)(scr + O_VD);
    float* KM   = scr + O_KM;
    float* KVS  = scr + O_KVS;
    float* KVO  = scr + O_KVO;
    __nv_bfloat16* OUT2H = (__nv_bfloat16*)(scr + O_OUT2H);
    float* S    = scr + O_S;
    __nv_bfloat16* SH  = (__nv_bfloat16*)(scr + O_SH);
    __nv_bfloat16* YH  = (__nv_bfloat16*)(scr + O_YH);
    __nv_bfloat16* Y2H = (__nv_bfloat16*)(scr + O_Y2H);
    float* SE   = scr + O_SE;
    float* INV  = scr + O_INV;
    float* PW   = scr + O_PW;
    __nv_bfloat16* WPJH = (__nv_bfloat16*)(scr + O_WPJH);
    __nv_bfloat16* WPIH = (__nv_bfloat16*)(scr + O_WPIH);
    __nv_bfloat16* WPOH = (__nv_bfloat16*)(scr + O_WPOH);
    __nv_bfloat16* WQH  = (__nv_bfloat16*)(scr + O_WQH);
    __nv_bfloat16* WKH  = (__nv_bfloat16*)(scr + O_WKH);

    static bool attr_set = false;
    if (!attr_set) {
        cudaFuncSetAttribute(gemm_qgkv_bf, cudaFuncAttributeMaxDynamicSharedMemorySize, SMEM_GBF);
        cudaFuncSetAttribute(gemm_bf<true>, cudaFuncAttributeMaxDynamicSharedMemorySize, SMEM_GBF);
        cudaFuncSetAttribute(gemm_bf_ln<256,true,false>,  cudaFuncAttributeMaxDynamicSharedMemorySize, SMEM_GBLN);
        cudaFuncSetAttribute(gemm_bf_ln<512,false,true>, cudaFuncAttributeMaxDynamicSharedMemorySize, SMEM_GBLN);
        cudaFuncSetAttribute(k_dw_glu, cudaFuncAttributeMaxDynamicSharedMemorySize, SMEM_DG);
        attr_set = true;
    }

    // 1. weight conversion + param prep
    k_cvtw<<<256, 256>>>(proj_w, WPJH, 256*256, pin_w, WPIH, 1024*256,
                         pout_w, WPOH, 256*512, qg_w, WQH, 512*256, kv_w, WKH, 512*256,
                         scale, power, INV, PW);
    // 2. src -> token-major (fp32 + bf16)
    k_tr_src<<<dim3(13, 8, BATCH), dim3(32, 32)>>>(src, XT, XTH);
    // 3. merged qg + kv GEMMs (ldmatrix)
    gemm_qgkv_bf<<<dim3(4, 200, 2), 256, SMEM_GBF>>>(XTH, WQH, qg_b, WKH, kv_b,
        pos, INV, PW, QP, QN, G, KP, KN, VF);
    // 4. fused: reductions + dwc5x5 + SE
    k_fused<<<1600, 256>>>(KP, KN, VF, KM, KVS, KVO, dwc_w, dwc_b, VD, src, se_w, SE);
    // 5. attention output + vd + gate -> bf16
    k_attn_out<<<512, 256>>>(QP, QN, KM, KVS, KVO, VD, G, OUT2H);
    // 6. proj + residual + LN1 -> S fp32 + SH bf16
    gemm_bf_ln<256,true,false><<<200, 512, SMEM_GBLN>>>(OUT2H, WPJH, proj_b, XT, ln1_w, ln1_b, S, SH);
    // 7. pin -> YH bf16
    gemm_bf<true><<<dim3(8, 200), 256, SMEM_GBF>>>(SH, WPIH, YH, TOKS, 1024, 256);
    // 8. dw3x3 + glu + se -> Y2H bf16
    k_dw_glu<<<dim3(4, 4, BATCH), 256, SMEM_DG>>>(YH, dw_w, SE, Y2H);
    // 9. pout + residual + LN2 -> NCHW output directly (transpose fused)
    gemm_bf_ln<512,false,true><<<200, 512, SMEM_GBLN>>>(Y2H, WPOH, nullptr, S, ln2_w, ln2_b, out, nullptr);
}